// round 1
// baseline (speedup 1.0000x reference)
#include <cuda_runtime.h>
#include <cuda_bf16.h>

#define NCELLS 8192
#define NCOLS  1024
#define CPC    8
#define ROWS_PER_BLOCK 8

// --------------------------------------------------------------------------
// Kernel 1: new_active + anomaly. One block of 1024 threads (1 per column).
// --------------------------------------------------------------------------
__global__ void htm_prep(const float* __restrict__ active_columns,
                         const float* __restrict__ predictive,
                         float* __restrict__ out_new_active,
                         float* __restrict__ out_anomaly) {
    __shared__ int s_cnt[2];  // [0]=num_active, [1]=num_predicted
    int c = threadIdx.x;
    if (c < 2) s_cnt[c] = 0;
    __syncthreads();

    float p[CPC];
    float s = 0.f;
#pragma unroll
    for (int k = 0; k < CPC; ++k) {
        p[k] = predictive[c * CPC + k];
        s += p[k];
    }
    bool has_pred = (s > 0.f);
    bool act = (active_columns[c] > 0.f);

#pragma unroll
    for (int k = 0; k < CPC; ++k) {
        float v = act ? (has_pred ? p[k] : 1.0f) : 0.0f;
        out_new_active[c * CPC + k] = v;
    }

    if (act) {
        atomicAdd(&s_cnt[0], 1);
        if (has_pred) atomicAdd(&s_cnt[1], 1);
    }
    __syncthreads();
    if (c == 0) {
        int na = s_cnt[0];
        int np = s_cnt[1];
        int den = na > 1 ? na : 1;
        out_anomaly[0] = 1.0f - (float)np / (float)den;
    }
}

// --------------------------------------------------------------------------
// Kernel 2: fused streaming pass over segment_weights.
//   - per row i: presyn[i] = sum_j (W[i,j] >= 0.5) * new_active[j]
//                new_predictive[i] = presyn >= 13
//   - Wout[i,j] = clip(W + prev[i] * fma(na[j], 0.11, -0.01), 0, 1)
//     (fma gives exactly +0.1f / -0.01f; prev=0 rows pass through exactly)
// Warp-per-row, 8 rows per 256-thread block. Vector loads (input aligned),
// scalar stores (output W region is misaligned: flat offset 16385 floats).
// --------------------------------------------------------------------------
__global__ void __launch_bounds__(256)
htm_main(const float* __restrict__ W,
         const float* __restrict__ prev,
         const float* __restrict__ na_g,
         float* __restrict__ Wout,
         float* __restrict__ pred_out) {
    __shared__ float4 s_na[NCELLS / 4];  // 32 KB

    const float4* na4 = (const float4*)na_g;
    for (int i = threadIdx.x; i < NCELLS / 4; i += 256)
        s_na[i] = na4[i];
    __syncthreads();

    int warp = threadIdx.x >> 5;
    int lane = threadIdx.x & 31;
    int row = blockIdx.x * ROWS_PER_BLOCK + warp;

    const float4* wrow = (const float4*)(W + (size_t)row * NCELLS);
    float* orow = Wout + (size_t)row * NCELLS;
    float prev_i = __ldg(prev + row);

    float cnt = 0.f;
#pragma unroll 4
    for (int i = lane; i < NCELLS / 4; i += 32) {
        float4 w = __ldcs(&wrow[i]);
        float4 n = s_na[i];

        if (w.x >= 0.5f) cnt += n.x;
        if (w.y >= 0.5f) cnt += n.y;
        if (w.z >= 0.5f) cnt += n.z;
        if (w.w >= 0.5f) cnt += n.w;

        float ox = fminf(fmaxf(fmaf(prev_i, fmaf(n.x, 0.11f, -0.01f), w.x), 0.f), 1.f);
        float oy = fminf(fmaxf(fmaf(prev_i, fmaf(n.y, 0.11f, -0.01f), w.y), 0.f), 1.f);
        float oz = fminf(fmaxf(fmaf(prev_i, fmaf(n.z, 0.11f, -0.01f), w.z), 0.f), 1.f);
        float ow = fminf(fmaxf(fmaf(prev_i, fmaf(n.w, 0.11f, -0.01f), w.w), 0.f), 1.f);

        int base = i * 4;
        __stcs(orow + base + 0, ox);
        __stcs(orow + base + 1, oy);
        __stcs(orow + base + 2, oz);
        __stcs(orow + base + 3, ow);
    }

    // warp-level presyn reduction (exact integer counts in f32)
#pragma unroll
    for (int o = 16; o; o >>= 1)
        cnt += __shfl_xor_sync(0xFFFFFFFFu, cnt, o);

    if (lane == 0)
        pred_out[row] = (cnt >= 13.0f) ? 1.0f : 0.0f;
}

// --------------------------------------------------------------------------
// Launch. Output layout (tuple order, flat):
//   [0 : 8192)                 new_active
//   [8192 : 16384)             new_predictive
//   [16384]                    anomaly
//   [16385 : 16385 + 8192^2)   new_segment_weights
// --------------------------------------------------------------------------
extern "C" void kernel_launch(void* const* d_in, const int* in_sizes, int n_in,
                              void* d_out, int out_size) {
    const float* active_columns = (const float*)d_in[0];
    const float* W              = (const float*)d_in[1];
    const float* predictive     = (const float*)d_in[2];
    const float* prev           = (const float*)d_in[3];

    float* out    = (float*)d_out;
    float* o_na   = out;
    float* o_pred = out + NCELLS;
    float* o_anom = out + 2 * NCELLS;
    float* o_W    = out + 2 * NCELLS + 1;

    htm_prep<<<1, NCOLS>>>(active_columns, predictive, o_na, o_anom);
    htm_main<<<NCELLS / ROWS_PER_BLOCK, 256>>>(W, prev, o_na, o_W, o_pred);
}